// round 7
// baseline (speedup 1.0000x reference)
#include <cuda_runtime.h>
#include <cuda_fp16.h>
#include <cstdint>

#define S_   128
#define N_   384
#define CM_  256
#define CH_  32
#define CZ_  128
#define P_   (N_*CH_)       // 12288
#define R_   (S_*N_)        // 49152

// Scratch (device globals)
__device__ __align__(128) float  g_a2 [S_*P_];           // [s][p] fp32
__device__ __align__(128) float  g_b2 [S_*P_];
__device__ __align__(128) __half g_a2T[(size_t)P_*S_];   // [p][s] fp16
__device__ __align__(128) __half g_b2T[(size_t)P_*S_];
__device__ __align__(128) __half g_w16T[32*128*32];      // [c][z][d] fp16
__device__ __align__(16)  float2 g_stats[R_];
__device__ __align__(16)  float  g_norm[N_*N_];

// ---------------- helpers ----------------
__device__ __forceinline__ uint32_t f2tf(float f){
    uint32_t u; asm("cvt.rna.tf32.f32 %0, %1;" : "=r"(u) : "f"(f)); return u;
}
__device__ __forceinline__ uint32_t cvta_smem(const void* p){
    uint32_t a; asm("{ .reg .u64 t; cvta.to.shared.u64 t, %1; cvt.u32.u64 %0, t; }" : "=r"(a) : "l"(p)); return a;
}
__device__ __forceinline__ void ldmx4(uint32_t& r0, uint32_t& r1, uint32_t& r2, uint32_t& r3, uint32_t addr){
    asm volatile("ldmatrix.sync.aligned.m8n8.x4.shared.b16 {%0,%1,%2,%3}, [%4];"
        : "=r"(r0), "=r"(r1), "=r"(r2), "=r"(r3) : "r"(addr));
}
__device__ __forceinline__ void mma8(float d[4], const uint32_t a[4], const uint32_t b[2], const float c[4]){
    asm volatile(
      "mma.sync.aligned.m16n8k8.row.col.f32.tf32.tf32.f32 "
      "{%0,%1,%2,%3},{%4,%5,%6,%7},{%8,%9},{%10,%11,%12,%13};\n"
      : "=f"(d[0]),"=f"(d[1]),"=f"(d[2]),"=f"(d[3])
      : "r"(a[0]),"r"(a[1]),"r"(a[2]),"r"(a[3]),
        "r"(b[0]),"r"(b[1]),
        "f"(c[0]),"f"(c[1]),"f"(c[2]),"f"(c[3]));
}
__device__ __forceinline__ void hmma16(float d[4], const uint32_t a[4], const uint32_t b[2]){
    asm volatile(
      "mma.sync.aligned.m16n8k16.row.col.f32.f16.f16.f32 "
      "{%0,%1,%2,%3},{%4,%5,%6,%7},{%8,%9},{%0,%1,%2,%3};\n"
      : "+f"(d[0]),"+f"(d[1]),"+f"(d[2]),"+f"(d[3])
      : "r"(a[0]),"r"(a[1]),"r"(a[2]),"r"(a[3]),
        "r"(b[0]),"r"(b[1]));
}
__device__ __forceinline__ void cpasync16(uint32_t dst, const void* src){
    asm volatile("cp.async.cg.shared.global [%0], [%1], 16;" :: "r"(dst), "l"(src) : "memory");
}

// ---------------------------------------------------------------------------
// K1a: per-row LayerNorm statistics
// ---------------------------------------------------------------------------
__global__ void k_stats(const float* __restrict__ m){
    int r = blockIdx.x*8 + (threadIdx.x>>5);
    int lane = threadIdx.x & 31;
    const float* row = m + (size_t)r*CM_;
    float s=0.f, s2=0.f;
#pragma unroll
    for (int j=0;j<8;j++){ float x = row[j*32+lane]; s += x; s2 += x*x; }
#pragma unroll
    for (int o=16;o;o>>=1){ s += __shfl_xor_sync(~0u,s,o); s2 += __shfl_xor_sync(~0u,s2,o); }
    if (lane==0){
        float mu = s*(1.f/CM_);
        float var = s2*(1.f/CM_) - mu*mu;
        g_stats[r] = make_float2(mu, rsqrtf(var + 1e-5f));
    }
}

// ---------------------------------------------------------------------------
// K0: norm[i,j]
// ---------------------------------------------------------------------------
__global__ void k_norm(const float* __restrict__ mask){
    __shared__ float mi[S_];
    int i = blockIdx.x, j = threadIdx.x;
    if (j < S_) mi[j] = mask[(size_t)j*N_ + i];
    __syncthreads();
    float acc = 0.f;
#pragma unroll 4
    for (int s=0;s<S_;s++) acc += mi[s]*mask[(size_t)s*N_ + j];
    g_norm[i*N_ + j] = acc + 1e-3f;
}

// ---------------------------------------------------------------------------
// K_w: w_out -> fp16, transposed per c-chunk: g_w16T[c][z][d]
// ---------------------------------------------------------------------------
__global__ void k_cvtw(const float* __restrict__ w_out){
    int o = blockIdx.x*256 + threadIdx.x;        // [c][z][d]
    int d = o & 31, z = (o>>5) & 127, c = o>>12;
    g_w16T[o] = __float2half(w_out[(size_t)(c*32+d)*CZ_ + z]);
}

// ---------------------------------------------------------------------------
// K1b: fused LN + dual projection (legacy tf32 mma)
// ---------------------------------------------------------------------------
__global__ __launch_bounds__(256) void k_proj(
    const float* __restrict__ m, const float* __restrict__ mask,
    const float* __restrict__ gamma, const float* __restrict__ beta,
    const float* __restrict__ w1, const float* __restrict__ b1,
    const float* __restrict__ w2, const float* __restrict__ b2)
{
    __shared__ float As[128][36];
    __shared__ float Bs[32][72];
    int r0 = blockIdx.x*128;
    int t = threadIdx.x, wid = t>>5, lane = t&31;
    int g = lane>>2, tig = lane&3;
    int wm = (wid&1)*64, wn = (wid>>1)*16;
    float acc[4][2][4] = {};

    for (int k0=0;k0<CM_;k0+=32){
#pragma unroll
        for (int q=0;q<4;q++){
            int f = t + q*256;
            int row = f>>3; int k4 = (f&7)*4;
            float4 x  = *(const float4*)(m + (size_t)(r0+row)*CM_ + k0 + k4);
            float2 st = g_stats[r0+row];
            float4 gm = *(const float4*)(gamma + k0 + k4);
            float4 bt = *(const float4*)(beta  + k0 + k4);
            float4 v;
            v.x = (x.x-st.x)*st.y*gm.x + bt.x;
            v.y = (x.y-st.x)*st.y*gm.y + bt.y;
            v.z = (x.z-st.x)*st.y*gm.z + bt.z;
            v.w = (x.w-st.x)*st.y*gm.w + bt.w;
            *(float4*)&As[row][k4] = v;
        }
#pragma unroll
        for (int q=0;q<2;q++){
            int f = t + q*256;
            int k_l = f>>4; int h4 = (f&15)*4;
            float4 w;
            if (h4 < 32) w = *(const float4*)(w1 + (size_t)(k0+k_l)*CH_ + h4);
            else         w = *(const float4*)(w2 + (size_t)(k0+k_l)*CH_ + (h4-32));
            *(float4*)&Bs[k_l][h4] = w;
        }
        __syncthreads();
#pragma unroll
        for (int kk=0;kk<32;kk+=8){
            uint32_t af[4][4], bfr[2][2];
#pragma unroll
            for (int mi=0;mi<4;mi++){
                int mb = wm + mi*16;
                af[mi][0]=f2tf(As[mb+g  ][kk+tig  ]);
                af[mi][1]=f2tf(As[mb+g+8][kk+tig  ]);
                af[mi][2]=f2tf(As[mb+g  ][kk+tig+4]);
                af[mi][3]=f2tf(As[mb+g+8][kk+tig+4]);
            }
#pragma unroll
            for (int ni=0;ni<2;ni++){
                int nb = wn + ni*8;
                bfr[ni][0]=f2tf(Bs[kk+tig  ][nb+g]);
                bfr[ni][1]=f2tf(Bs[kk+tig+4][nb+g]);
            }
#pragma unroll
            for (int mi=0;mi<4;mi++)
#pragma unroll
                for (int ni=0;ni<2;ni++)
                    mma8(acc[mi][ni], af[mi], bfr[ni], acc[mi][ni]);
        }
        __syncthreads();
    }
#pragma unroll
    for (int mi=0;mi<4;mi++){
#pragma unroll
        for (int ni=0;ni<2;ni++){
            int h0 = wn + ni*8 + tig*2;
#pragma unroll
            for (int half=0; half<2; half++){
                int r = r0 + wm + mi*16 + g + half*8;
                int s_ = r / N_;
                int n_ = r - s_*N_;
                float mv = mask[(size_t)s_*N_ + n_];
#pragma unroll
                for (int e=0;e<2;e++){
                    int h = h0 + e;
                    float v = acc[mi][ni][half*2+e];
                    if (h < CH_) g_a2[(size_t)s_*P_ + n_*CH_ + h]       = (v + __ldg(&b1[h]))*mv;
                    else         g_b2[(size_t)s_*P_ + n_*CH_ + (h-CH_)] = (v + __ldg(&b2[h-CH_]))*mv;
                }
            }
        }
    }
}

// ---------------------------------------------------------------------------
// K_tr: transpose a2/b2 [S][P] fp32 -> [P][S] fp16
// ---------------------------------------------------------------------------
__global__ void k_tr(){
    __shared__ float tl[32][33];
    const float* src = blockIdx.z ? g_b2 : g_a2;
    __half*      dst = blockIdx.z ? g_b2T : g_a2T;
    int x = blockIdx.x*32 + threadIdx.x;
    int y0 = blockIdx.y*32;
#pragma unroll
    for (int i=0;i<4;i++)
        tl[threadIdx.y + i*8][threadIdx.x] = src[(size_t)(y0+threadIdx.y+i*8)*P_ + x];
    __syncthreads();
#pragma unroll
    for (int i=0;i<4;i++)
        dst[(size_t)(blockIdx.x*32 + threadIdx.y + i*8)*S_ + y0 + threadIdx.x]
            = __float2half(tl[threadIdx.x][threadIdx.y + i*8]);
}

// ---------------------------------------------------------------------------
// K_fused v2: CTA = (16 i, 4 j). smem 111.6KB -> 2 CTAs/SM. cp.async loads.
// ---------------------------------------------------------------------------
#define BSTR 136   // Bs/As row stride (halves)
#define WSTR 72    // Ws row stride
#define CSTR 176   // Cc row stride (j-substride 40); ≡16 mod 32 -> ldm conflict-free
#define BS_OFF 0
#define AS_OFF (128*BSTR)                 // 17408
#define WS_OFF (AS_OFF + 2*32*BSTR)       // 26112
#define CC_OFF (WS_OFF + 2*128*WSTR)      // 44544
#define SMH_TOT (CC_OFF + 2*32*CSTR)      // 55808 halves = 111616 B

// issue async loads for c-chunk c0 into buffer buf
__device__ __forceinline__ void issue_loads(int c0, int buf, int i0, int t,
                                            uint32_t as_raw, uint32_t ws_raw){
#pragma unroll
    for (int q=0;q<2;q++){
        int idx = t + q*256;
        int row = idx>>4, u = idx&15;
        int p = (i0 + (row>>1))*CH_ + c0 + (row&1);
        cpasync16(as_raw + (uint32_t)((buf*32*BSTR + row*BSTR + u*8)*2),
                  g_a2T + (size_t)p*S_ + u*8);
    }
#pragma unroll
    for (int q=0;q<4;q++){
        int idx = t + q*256;
        int cp = idx>>9, z = (idx>>2)&127, du = idx&3;
        cpasync16(ws_raw + (uint32_t)((buf*128*WSTR + z*WSTR + cp*32 + du*8)*2),
                  g_w16T + (size_t)(c0+cp)*4096 + z*32 + du*8);
    }
    asm volatile("cp.async.commit_group;" ::: "memory");
}

// GEMM1: Cc[32 rows=(i,cp)][128 q] = A_chunk @ Bs^T
__device__ __forceinline__ void gemm1_chunk(uint32_t ab, uint32_t bs_b, __half* Cb,
                                            int wm1, int wn1, int lrow, int lcol,
                                            int g, int tig){
    float acc1[4][4] = {};
#pragma unroll
    for (int kk=0;kk<8;kk++){
        int k0 = kk*16;
        uint32_t af[4], bf[4][2];
        ldmx4(af[0],af[1],af[2],af[3], ab + (uint32_t)(((wm1+lrow)*BSTR + k0 + lcol)*2));
#pragma unroll
        for (int np=0;np<2;np++){
            uint32_t r0,r1,r2,r3;
            ldmx4(r0,r1,r2,r3, bs_b + (uint32_t)(((wn1+np*16+lrow)*BSTR + k0 + lcol)*2));
            bf[np*2  ][0]=r0; bf[np*2  ][1]=r2;
            bf[np*2+1][0]=r1; bf[np*2+1][1]=r3;
        }
#pragma unroll
        for (int ni=0;ni<4;ni++) hmma16(acc1[ni], af, bf[ni]);
    }
#pragma unroll
    for (int ni=0;ni<4;ni++){
        int q = wn1 + ni*8 + tig*2;
        int col = (q>>5)*40 + (q&31);
#pragma unroll
        for (int half=0; half<2; half++){
            int mr = wm1 + g + half*8;
            *(__half2*)&Cb[mr*CSTR + col] =
                __floats2half2_rn(acc1[ni][half*2+0], acc1[ni][half*2+1]);
        }
    }
}

__global__ __launch_bounds__(256,2) void k_fused(const float* __restrict__ bout,
                                                 float* __restrict__ out)
{
    extern __shared__ __align__(16) __half sf[];
    __half* Bs = sf + BS_OFF;
    __half* Cc = sf + CC_OFF;

    const int t = threadIdx.x, wid = t>>5, lane = t&31;
    const int g = lane>>2, tig = lane&3;
    const int lrow = lane&15, lcol = (lane>>4)*8;
    const int j0 = blockIdx.x*4, i0 = blockIdx.y*16;

    const uint32_t bs_b = cvta_smem(sf) + BS_OFF*2;
    const uint32_t as_raw = cvta_smem(sf) + AS_OFF*2;
    const uint32_t ws_raw = cvta_smem(sf) + WS_OFF*2;
    const uint32_t cc_b = cvta_smem(sf) + CC_OFF*2;

    const int wm1 = (wid&1)*16, wn1 = (wid>>1)*32;   // GEMM1: M=32, N=128
    const int wm2 = wid&3,      wn2 = (wid>>2)*64;   // GEMM2: M=64 pairs, N=128 z

    // resident B slice: 128 q-rows x 128 s
#pragma unroll
    for (int q=0;q<8;q++){
        int idx = t + q*256;
        int row = idx>>4, u = idx&15;
        *(uint4*)&Bs[row*BSTR + u*8] = *(const uint4*)(g_b2T + (size_t)(j0*32+row)*S_ + u*8);
    }

    issue_loads(0, 0, i0, t, as_raw, ws_raw);
    asm volatile("cp.async.wait_group 0;" ::: "memory");
    __syncthreads();

    float acc2[8][4];
#pragma unroll
    for (int a=0;a<8;a++){ acc2[a][0]=0.f; acc2[a][1]=0.f; acc2[a][2]=0.f; acc2[a][3]=0.f; }

    gemm1_chunk(as_raw, bs_b, Cc, wm1, wn1, lrow, lcol, g, tig);

    for (int k=0;k<16;k++){
        int bc = k&1;
        if (k<15) issue_loads((k+1)*2, bc^1, i0, t, as_raw, ws_raw);
        __syncthreads();   // Cc[bc] stores visible

        // ---- GEMM2 chunk k ----
        {
            uint32_t cb = cc_b + (uint32_t)(bc*32*CSTR*2);
            uint32_t wb = ws_raw + (uint32_t)(bc*128*WSTR*2);
#pragma unroll
            for (int kk=0;kk<4;kk++){
                int cp = kk>>1, dh = (kk&1)*16;
                uint32_t af[4], bf[8][2];
                ldmx4(af[0],af[1],af[2],af[3],
                      cb + (uint32_t)(((((wm2*4 + (lrow>>2))*2) + cp)*CSTR + (lrow&3)*40 + dh + lcol)*2));
#pragma unroll
                for (int np=0;np<4;np++){
                    uint32_t r0,r1,r2,r3;
                    ldmx4(r0,r1,r2,r3, wb + (uint32_t)(((wn2+np*16+lrow)*WSTR + cp*32 + dh + lcol)*2));
                    bf[np*2  ][0]=r0; bf[np*2  ][1]=r2;
                    bf[np*2+1][0]=r1; bf[np*2+1][1]=r3;
                }
#pragma unroll
                for (int ni=0;ni<8;ni++) hmma16(acc2[ni], af, bf[ni]);
            }
        }

        if (k<15){
            asm volatile("cp.async.wait_group 0;" ::: "memory");
            __syncthreads();   // A/W(k+1) ready; Cc[bc^1] free
            gemm1_chunk(as_raw + (uint32_t)((bc^1)*32*BSTR*2), bs_b,
                        Cc + (bc^1)*32*CSTR, wm1, wn1, lrow, lcol, g, tig);
        }
    }

    // ---- epilogue: bias + norm ----
#pragma unroll
    for (int ni=0;ni<8;ni++){
        int z = wn2 + ni*8 + tig*2;
        float bo0 = __ldg(&bout[z]), bo1 = __ldg(&bout[z+1]);
#pragma unroll
        for (int half=0; half<2; half++){
            int mrow = g + half*8;
            int i = i0 + wm2*4 + (mrow>>2);
            int j = j0 + (mrow&3);
            float inv = 1.f / g_norm[i*N_ + j];
            float2 v = make_float2((acc2[ni][half*2+0] + bo0)*inv,
                                   (acc2[ni][half*2+1] + bo1)*inv);
            *(float2*)&out[((size_t)i*N_ + j)*CZ_ + z] = v;
        }
    }
}

// ---------------------------------------------------------------------------
extern "C" void kernel_launch(void* const* d_in, const int* in_sizes, int n_in,
                              void* d_out, int out_size)
{
    const float* m     = (const float*)d_in[0];
    const float* mask  = (const float*)d_in[1];
    const float* gamma = (const float*)d_in[2];
    const float* beta  = (const float*)d_in[3];
    const float* w1    = (const float*)d_in[4];
    const float* b1    = (const float*)d_in[5];
    const float* w2    = (const float*)d_in[6];
    const float* b2    = (const float*)d_in[7];
    const float* w_out = (const float*)d_in[8];
    const float* b_out = (const float*)d_in[9];
    float* out = (float*)d_out;

    const int fsmem = SMH_TOT*2;  // 111616 bytes
    cudaFuncSetAttribute(k_fused, cudaFuncAttributeMaxDynamicSharedMemorySize, fsmem);

    k_stats<<<R_/8, 256>>>(m);
    k_norm<<<N_, N_>>>(mask);
    k_cvtw<<<(32*128*32)/256, 256>>>(w_out);
    k_proj<<<R_/128, 256>>>(m, mask, gamma, beta, w1, b1, w2, b2);
    dim3 gt(P_/32, S_/32, 2);
    k_tr<<<gt, dim3(32,8)>>>();
    dim3 gf(N_/4, N_/16);
    k_fused<<<gf, 256, fsmem>>>(b_out, out);
}

// round 8
// speedup vs baseline: 1.0319x; 1.0319x over previous
#include <cuda_runtime.h>
#include <cuda_fp16.h>
#include <cstdint>

#define S_   128
#define N_   384
#define CM_  256
#define CH_  32
#define CZ_  128
#define P_   (N_*CH_)       // 12288
#define R_   (S_*N_)        // 49152

// Scratch (device globals)
__device__ __align__(128) float  g_a2 [S_*P_];           // [s][p] fp32
__device__ __align__(128) float  g_b2 [S_*P_];
__device__ __align__(128) __half g_a2T[(size_t)P_*S_];   // [p][s] fp16
__device__ __align__(128) __half g_b2T[(size_t)P_*S_];
__device__ __align__(128) __half g_w16T[32*128*32];      // [c][z][d] fp16
__device__ __align__(16)  float2 g_stats[R_];
__device__ __align__(16)  float  g_norm[N_*N_];

// ---------------- helpers ----------------
__device__ __forceinline__ uint32_t f2tf(float f){
    uint32_t u; asm("cvt.rna.tf32.f32 %0, %1;" : "=r"(u) : "f"(f)); return u;
}
__device__ __forceinline__ uint32_t cvta_smem(const void* p){
    uint32_t a; asm("{ .reg .u64 t; cvta.to.shared.u64 t, %1; cvt.u32.u64 %0, t; }" : "=r"(a) : "l"(p)); return a;
}
__device__ __forceinline__ void ldmx4(uint32_t& r0, uint32_t& r1, uint32_t& r2, uint32_t& r3, uint32_t addr){
    asm volatile("ldmatrix.sync.aligned.m8n8.x4.shared.b16 {%0,%1,%2,%3}, [%4];"
        : "=r"(r0), "=r"(r1), "=r"(r2), "=r"(r3) : "r"(addr));
}
__device__ __forceinline__ void mma8(float d[4], const uint32_t a[4], const uint32_t b[2], const float c[4]){
    asm volatile(
      "mma.sync.aligned.m16n8k8.row.col.f32.tf32.tf32.f32 "
      "{%0,%1,%2,%3},{%4,%5,%6,%7},{%8,%9},{%10,%11,%12,%13};\n"
      : "=f"(d[0]),"=f"(d[1]),"=f"(d[2]),"=f"(d[3])
      : "r"(a[0]),"r"(a[1]),"r"(a[2]),"r"(a[3]),
        "r"(b[0]),"r"(b[1]),
        "f"(c[0]),"f"(c[1]),"f"(c[2]),"f"(c[3]));
}
__device__ __forceinline__ void hmma16(float d[4], const uint32_t a[4], const uint32_t b[2]){
    asm volatile(
      "mma.sync.aligned.m16n8k16.row.col.f32.f16.f16.f32 "
      "{%0,%1,%2,%3},{%4,%5,%6,%7},{%8,%9},{%0,%1,%2,%3};\n"
      : "+f"(d[0]),"+f"(d[1]),"+f"(d[2]),"+f"(d[3])
      : "r"(a[0]),"r"(a[1]),"r"(a[2]),"r"(a[3]),
        "r"(b[0]),"r"(b[1]));
}
__device__ __forceinline__ void cpasync16(uint32_t dst, const void* src){
    asm volatile("cp.async.cg.shared.global [%0], [%1], 16;" :: "r"(dst), "l"(src) : "memory");
}

// ---------------------------------------------------------------------------
// K1a: per-row LayerNorm statistics
// ---------------------------------------------------------------------------
__global__ void k_stats(const float* __restrict__ m){
    int r = blockIdx.x*8 + (threadIdx.x>>5);
    int lane = threadIdx.x & 31;
    const float* row = m + (size_t)r*CM_;
    float s=0.f, s2=0.f;
#pragma unroll
    for (int j=0;j<8;j++){ float x = row[j*32+lane]; s += x; s2 += x*x; }
#pragma unroll
    for (int o=16;o;o>>=1){ s += __shfl_xor_sync(~0u,s,o); s2 += __shfl_xor_sync(~0u,s2,o); }
    if (lane==0){
        float mu = s*(1.f/CM_);
        float var = s2*(1.f/CM_) - mu*mu;
        g_stats[r] = make_float2(mu, rsqrtf(var + 1e-5f));
    }
}

// ---------------------------------------------------------------------------
// K0: norm[i,j]
// ---------------------------------------------------------------------------
__global__ void k_norm(const float* __restrict__ mask){
    __shared__ float mi[S_];
    int i = blockIdx.x, j = threadIdx.x;
    if (j < S_) mi[j] = mask[(size_t)j*N_ + i];
    __syncthreads();
    float acc = 0.f;
#pragma unroll 4
    for (int s=0;s<S_;s++) acc += mi[s]*mask[(size_t)s*N_ + j];
    g_norm[i*N_ + j] = acc + 1e-3f;
}

// ---------------------------------------------------------------------------
// K_w: w_out -> fp16, transposed per c-chunk: g_w16T[c][z][d]
// ---------------------------------------------------------------------------
__global__ void k_cvtw(const float* __restrict__ w_out){
    int o = blockIdx.x*256 + threadIdx.x;        // [c][z][d]
    int d = o & 31, z = (o>>5) & 127, c = o>>12;
    g_w16T[o] = __float2half(w_out[(size_t)(c*32+d)*CZ_ + z]);
}

// ---------------------------------------------------------------------------
// K1b: fused LN + dual projection (legacy tf32 mma)
// ---------------------------------------------------------------------------
__global__ __launch_bounds__(256) void k_proj(
    const float* __restrict__ m, const float* __restrict__ mask,
    const float* __restrict__ gamma, const float* __restrict__ beta,
    const float* __restrict__ w1, const float* __restrict__ b1,
    const float* __restrict__ w2, const float* __restrict__ b2)
{
    __shared__ float As[128][36];
    __shared__ float Bs[32][72];
    int r0 = blockIdx.x*128;
    int t = threadIdx.x, wid = t>>5, lane = t&31;
    int g = lane>>2, tig = lane&3;
    int wm = (wid&1)*64, wn = (wid>>1)*16;
    float acc[4][2][4] = {};

    for (int k0=0;k0<CM_;k0+=32){
#pragma unroll
        for (int q=0;q<4;q++){
            int f = t + q*256;
            int row = f>>3; int k4 = (f&7)*4;
            float4 x  = *(const float4*)(m + (size_t)(r0+row)*CM_ + k0 + k4);
            float2 st = g_stats[r0+row];
            float4 gm = *(const float4*)(gamma + k0 + k4);
            float4 bt = *(const float4*)(beta  + k0 + k4);
            float4 v;
            v.x = (x.x-st.x)*st.y*gm.x + bt.x;
            v.y = (x.y-st.x)*st.y*gm.y + bt.y;
            v.z = (x.z-st.x)*st.y*gm.z + bt.z;
            v.w = (x.w-st.x)*st.y*gm.w + bt.w;
            *(float4*)&As[row][k4] = v;
        }
#pragma unroll
        for (int q=0;q<2;q++){
            int f = t + q*256;
            int k_l = f>>4; int h4 = (f&15)*4;
            float4 w;
            if (h4 < 32) w = *(const float4*)(w1 + (size_t)(k0+k_l)*CH_ + h4);
            else         w = *(const float4*)(w2 + (size_t)(k0+k_l)*CH_ + (h4-32));
            *(float4*)&Bs[k_l][h4] = w;
        }
        __syncthreads();
#pragma unroll
        for (int kk=0;kk<32;kk+=8){
            uint32_t af[4][4], bfr[2][2];
#pragma unroll
            for (int mi=0;mi<4;mi++){
                int mb = wm + mi*16;
                af[mi][0]=f2tf(As[mb+g  ][kk+tig  ]);
                af[mi][1]=f2tf(As[mb+g+8][kk+tig  ]);
                af[mi][2]=f2tf(As[mb+g  ][kk+tig+4]);
                af[mi][3]=f2tf(As[mb+g+8][kk+tig+4]);
            }
#pragma unroll
            for (int ni=0;ni<2;ni++){
                int nb = wn + ni*8;
                bfr[ni][0]=f2tf(Bs[kk+tig  ][nb+g]);
                bfr[ni][1]=f2tf(Bs[kk+tig+4][nb+g]);
            }
#pragma unroll
            for (int mi=0;mi<4;mi++)
#pragma unroll
                for (int ni=0;ni<2;ni++)
                    mma8(acc[mi][ni], af[mi], bfr[ni], acc[mi][ni]);
        }
        __syncthreads();
    }
#pragma unroll
    for (int mi=0;mi<4;mi++){
#pragma unroll
        for (int ni=0;ni<2;ni++){
            int h0 = wn + ni*8 + tig*2;
#pragma unroll
            for (int half=0; half<2; half++){
                int r = r0 + wm + mi*16 + g + half*8;
                int s_ = r / N_;
                int n_ = r - s_*N_;
                float mv = mask[(size_t)s_*N_ + n_];
#pragma unroll
                for (int e=0;e<2;e++){
                    int h = h0 + e;
                    float v = acc[mi][ni][half*2+e];
                    if (h < CH_) g_a2[(size_t)s_*P_ + n_*CH_ + h]       = (v + __ldg(&b1[h]))*mv;
                    else         g_b2[(size_t)s_*P_ + n_*CH_ + (h-CH_)] = (v + __ldg(&b2[h-CH_]))*mv;
                }
            }
        }
    }
}

// ---------------------------------------------------------------------------
// K_tr: transpose a2/b2 [S][P] fp32 -> [P][S] fp16
// ---------------------------------------------------------------------------
__global__ void k_tr(){
    __shared__ float tl[32][33];
    const float* src = blockIdx.z ? g_b2 : g_a2;
    __half*      dst = blockIdx.z ? g_b2T : g_a2T;
    int x = blockIdx.x*32 + threadIdx.x;
    int y0 = blockIdx.y*32;
#pragma unroll
    for (int i=0;i<4;i++)
        tl[threadIdx.y + i*8][threadIdx.x] = src[(size_t)(y0+threadIdx.y+i*8)*P_ + x];
    __syncthreads();
#pragma unroll
    for (int i=0;i<4;i++)
        dst[(size_t)(blockIdx.x*32 + threadIdx.y + i*8)*S_ + y0 + threadIdx.x]
            = __float2half(tl[threadIdx.x][threadIdx.y + i*8]);
}

// ---------------------------------------------------------------------------
// K_fused v3: CTA=(16 i, 8 j), 512 threads, cp.async chunk loads.
// ---------------------------------------------------------------------------
#define BSTR 136   // Bs/As row stride (halves)
#define WSTR 72    // Ws row stride
#define CSTR 328   // Cc row stride (j-substride 40)
#define BS_OFF 0
#define AS_OFF (256*BSTR)                 // 34816
#define WS_OFF (AS_OFF + 2*32*BSTR)       // +8704
#define CC_OFF (WS_OFF + 2*128*WSTR)      // +18432
#define SMH_TOT (CC_OFF + 2*32*CSTR)      // 82944 halves = 165888 B
#define NT 512

// async loads for c-chunk c0 into buffer buf (512 threads)
__device__ __forceinline__ void issue_loads(int c0, int buf, int i0, int t,
                                            uint32_t as_raw, uint32_t ws_raw){
    {   // A: 32 rows x 128 halves = 512 uint4, 1/thread
        int row = t>>4, u = t&15;
        int p = (i0 + (row>>1))*CH_ + c0 + (row&1);
        cpasync16(as_raw + (uint32_t)((buf*32*BSTR + row*BSTR + u*8)*2),
                  g_a2T + (size_t)p*S_ + u*8);
    }
#pragma unroll
    for (int q=0;q<2;q++){  // W: 2cp x 128z x 32d = 1024 uint4, 2/thread
        int idx = t + q*NT;
        int cp = idx>>9, z = (idx>>2)&127, du = idx&3;
        cpasync16(ws_raw + (uint32_t)((buf*128*WSTR + z*WSTR + cp*32 + du*8)*2),
                  g_w16T + (size_t)(c0+cp)*4096 + z*32 + du*8);
    }
    asm volatile("cp.async.commit_group;" ::: "memory");
}

// GEMM1: Cc[32 rows=(i,cp)][256 q] = A_chunk @ Bs^T; 16 warps: 2m x 8n
__device__ __forceinline__ void gemm1_chunk(uint32_t ab, uint32_t bs_b, __half* Cb,
                                            int wm1, int wn1, int lrow, int lcol,
                                            int g, int tig){
    float acc1[4][4] = {};
#pragma unroll
    for (int kk=0;kk<8;kk++){
        int k0 = kk*16;
        uint32_t af[4], bf[4][2];
        ldmx4(af[0],af[1],af[2],af[3], ab + (uint32_t)(((wm1+lrow)*BSTR + k0 + lcol)*2));
#pragma unroll
        for (int np=0;np<2;np++){
            uint32_t r0,r1,r2,r3;
            ldmx4(r0,r1,r2,r3, bs_b + (uint32_t)(((wn1+np*16+lrow)*BSTR + k0 + lcol)*2));
            bf[np*2  ][0]=r0; bf[np*2  ][1]=r2;
            bf[np*2+1][0]=r1; bf[np*2+1][1]=r3;
        }
#pragma unroll
        for (int ni=0;ni<4;ni++) hmma16(acc1[ni], af, bf[ni]);
    }
#pragma unroll
    for (int ni=0;ni<4;ni++){
        int q = wn1 + ni*8 + tig*2;
        int col = (q>>5)*40 + (q&31);
#pragma unroll
        for (int half=0; half<2; half++){
            int mr = wm1 + g + half*8;
            *(__half2*)&Cb[mr*CSTR + col] =
                __floats2half2_rn(acc1[ni][half*2+0], acc1[ni][half*2+1]);
        }
    }
}

__global__ __launch_bounds__(NT,1) void k_fused(const float* __restrict__ bout,
                                                float* __restrict__ out)
{
    extern __shared__ __align__(16) __half sf[];
    __half* Bs = sf + BS_OFF;
    __half* Cc = sf + CC_OFF;

    const int t = threadIdx.x, wid = t>>5, lane = t&31;
    const int g = lane>>2, tig = lane&3;
    const int lrow = lane&15, lcol = (lane>>4)*8;
    const int j0 = blockIdx.x*8, i0 = blockIdx.y*16;

    const uint32_t sb = cvta_smem(sf);
    const uint32_t bs_b = sb + BS_OFF*2;
    const uint32_t as_raw = sb + AS_OFF*2;
    const uint32_t ws_raw = sb + WS_OFF*2;
    const uint32_t cc_b = sb + CC_OFF*2;

    const int wm1 = (wid&1)*16, wn1 = (wid>>1)*32;   // GEMM1: 2m x 8n
    const int wm2 = (wid&7)*16, wn2 = (wid>>3)*64;   // GEMM2: 8m x 2n

    // resident B slice: 256 q-rows x 128 s = 4096 uint4, 8/thread
#pragma unroll
    for (int q=0;q<8;q++){
        int idx = t + q*NT;
        int row = idx>>4, u = idx&15;
        *(uint4*)&Bs[row*BSTR + u*8] = *(const uint4*)(g_b2T + (size_t)(j0*32+row)*S_ + u*8);
    }

    issue_loads(0, 0, i0, t, as_raw, ws_raw);
    asm volatile("cp.async.wait_group 0;" ::: "memory");
    __syncthreads();

    float acc2[8][4];
#pragma unroll
    for (int a=0;a<8;a++){ acc2[a][0]=0.f; acc2[a][1]=0.f; acc2[a][2]=0.f; acc2[a][3]=0.f; }

    gemm1_chunk(as_raw, bs_b, Cc, wm1, wn1, lrow, lcol, g, tig);

    for (int k=0;k<16;k++){
        int bc = k&1;
        if (k<15) issue_loads((k+1)*2, bc^1, i0, t, as_raw, ws_raw);
        __syncthreads();   // Cc(k) stores visible

        // ---- GEMM2 chunk k: warp tile m16 x n64 ----
        {
            uint32_t cb = cc_b + (uint32_t)(bc*32*CSTR*2);
            uint32_t wb = ws_raw + (uint32_t)(bc*128*WSTR*2);
            int prow = wm2 + lrow;
            int arow0 = ((prow>>3)*2)*CSTR + (prow&7)*40;
#pragma unroll
            for (int kk=0;kk<4;kk++){
                int cp = kk>>1, dh = (kk&1)*16;
                uint32_t af[4], bf[8][2];
                ldmx4(af[0],af[1],af[2],af[3],
                      cb + (uint32_t)((arow0 + cp*CSTR + dh + lcol)*2));
#pragma unroll
                for (int np=0;np<4;np++){
                    uint32_t r0,r1,r2,r3;
                    ldmx4(r0,r1,r2,r3, wb + (uint32_t)(((wn2+np*16+lrow)*WSTR + cp*32 + dh + lcol)*2));
                    bf[np*2  ][0]=r0; bf[np*2  ][1]=r2;
                    bf[np*2+1][0]=r1; bf[np*2+1][1]=r3;
                }
#pragma unroll
                for (int ni=0;ni<8;ni++) hmma16(acc2[ni], af, bf[ni]);
            }
        }

        if (k<15){
            asm volatile("cp.async.wait_group 0;" ::: "memory");
            __syncthreads();   // A/W(k+1) ready; Cc[bc^1] free
            gemm1_chunk(as_raw + (uint32_t)((bc^1)*32*BSTR*2), bs_b,
                        Cc + (bc^1)*32*CSTR, wm1, wn1, lrow, lcol, g, tig);
        }
    }

    // ---- epilogue: bias + norm ----
#pragma unroll
    for (int ni=0;ni<8;ni++){
        int z = wn2 + ni*8 + tig*2;
        float bo0 = __ldg(&bout[z]), bo1 = __ldg(&bout[z+1]);
#pragma unroll
        for (int half=0; half<2; half++){
            int pr = wm2 + g + half*8;
            int i = i0 + (pr>>3);
            int j = j0 + (pr&7);
            float inv = 1.f / g_norm[i*N_ + j];
            float2 v = make_float2((acc2[ni][half*2+0] + bo0)*inv,
                                   (acc2[ni][half*2+1] + bo1)*inv);
            *(float2*)&out[((size_t)i*N_ + j)*CZ_ + z] = v;
        }
    }
}

// ---------------------------------------------------------------------------
extern "C" void kernel_launch(void* const* d_in, const int* in_sizes, int n_in,
                              void* d_out, int out_size)
{
    const float* m     = (const float*)d_in[0];
    const float* mask  = (const float*)d_in[1];
    const float* gamma = (const float*)d_in[2];
    const float* beta  = (const float*)d_in[3];
    const float* w1    = (const float*)d_in[4];
    const float* b1    = (const float*)d_in[5];
    const float* w2    = (const float*)d_in[6];
    const float* b2    = (const float*)d_in[7];
    const float* w_out = (const float*)d_in[8];
    const float* b_out = (const float*)d_in[9];
    float* out = (float*)d_out;

    const int fsmem = SMH_TOT*2;  // 165888 bytes
    cudaFuncSetAttribute(k_fused, cudaFuncAttributeMaxDynamicSharedMemorySize, fsmem);

    k_stats<<<R_/8, 256>>>(m);
    k_norm<<<N_, N_>>>(mask);
    k_cvtw<<<(32*128*32)/256, 256>>>(w_out);
    k_proj<<<R_/128, 256>>>(m, mask, gamma, beta, w1, b1, w2, b2);
    dim3 gt(P_/32, S_/32, 2);
    k_tr<<<gt, dim3(32,8)>>>();
    dim3 gf(N_/8, N_/16);
    k_fused<<<gf, NT, fsmem>>>(b_out, out);
}